// round 15
// baseline (speedup 1.0000x reference)
#include <cuda_runtime.h>
#include <cuda_fp16.h>
#include <math_constants.h>
#include <stdint.h>

#define HW    3600
#define WDIM  60
#define CCH   128
#define NBATCH 4
#define KTOP  100
#define CAP   65536
#define NBY   29
#define NBXS  57
#define NBX   29
#define LCPARTS 15
#define SPH   136
#define SPHB  72

// ---------------- device scratch ----------------
__device__ float g_sm[(size_t)NBATCH * HW * HW];
__device__ float g_rp[NBATCH * NBXS * HW];
__device__ float g_cp[NBATCH * NBY * HW];
__device__ float g_vp[NBATCH * NBXS * HW];
__device__ float g_LR[NBATCH * HW];
__device__ float g_LC[NBATCH * HW];
__device__ float g_vmax[NBATCH * HW];
__device__ float g_rowbound[NBATCH * HW];
__device__ float g_lcmin_blk[NBATCH * NBX];
__device__ float g_lcmax_part[NBATCH * LCPARTS];
__device__ float g_thrv[NBATCH];
__device__ int   g_cnt[NBATCH];
__device__ int   g_rowcnt[NBATCH];
__device__ int   g_rowlist[NBATCH * HW];
__device__ float g_cv[NBATCH * CAP];
__device__ int   g_ci[NBATCH * CAP];
__device__ int   g_topi[NBATCH * KTOP];

// ---------------- helpers ----------------
__device__ __forceinline__ void mma_f16(float c[4], const unsigned a[4], const unsigned b[2]) {
    asm volatile(
        "mma.sync.aligned.m16n8k16.row.col.f32.f16.f16.f32 "
        "{%0,%1,%2,%3}, {%4,%5,%6,%7}, {%8,%9}, {%0,%1,%2,%3};"
        : "+f"(c[0]), "+f"(c[1]), "+f"(c[2]), "+f"(c[3])
        : "r"(a[0]), "r"(a[1]), "r"(a[2]), "r"(a[3]), "r"(b[0]), "r"(b[1]));
}
__device__ __forceinline__ unsigned mono_bits(float f) {
    unsigned b = __float_as_uint(f);
    return (b & 0x80000000u) ? ~b : (b | 0x80000000u);
}
__device__ __forceinline__ unsigned h2u(__half2 h) {
    return *reinterpret_cast<unsigned*>(&h);
}

// ---------------- GEMM: fp16 x3 split, 128x64 tile, 256 thr, 2 CTA/SM ----------------
__global__ __launch_bounds__(256, 2) void gemm_kernel(const float* __restrict__ x, int n) {
    __shared__ __align__(16) __half2 Ah[2][8][SPH];
    __shared__ __align__(16) __half2 Al[2][8][SPH];
    __shared__ __align__(16) __half2 Bh[2][8][SPHB];
    __shared__ __align__(16) __half2 Bl[2][8][SPHB];
    __shared__ float s_rs[2][128];
    __shared__ float s_rm[2][128];
    __shared__ float s_cs[4][64];

    const int l0 = blockIdx.y * 128;
    const int s0 = blockIdx.x * 64;
    const float* A = x + (size_t)n * CCH * HW;
    const float* B = x + (size_t)(n + NBATCH) * CCH * HW;
    const int tid = threadIdx.x;
    const int lane = tid & 31;
    const int wid = tid >> 5;
    const int g = lane >> 2, tig = lane & 3;
    const int wm = wid & 3, wn = wid >> 2;
    const int rb = wm * 32, cb = wn * 32;

    const int kpA = tid >> 5;
    const int m0A = (lane) << 2;
    const bool okA = (l0 + m0A) < HW;
    const int kpB = (tid & 127) >> 4;
    const int m0B = (tid & 15) << 2;
    const bool doB = tid < 128;
    const bool okB = (s0 + m0B) < HW;

    float acc[2][4][4];
#pragma unroll
    for (int mi = 0; mi < 2; mi++)
#pragma unroll
        for (int ni = 0; ni < 4; ni++)
#pragma unroll
            for (int q = 0; q < 4; q++) acc[mi][ni][q] = 0.0f;

    float4 rA0, rA1, rB0, rB1;

    auto ldg_chunk = [&](int c) {
        const int dA = c * 16 + kpA * 2;
        rA0 = okA ? *reinterpret_cast<const float4*>(A + (size_t)dA * HW + l0 + m0A)
                  : make_float4(0.f, 0.f, 0.f, 0.f);
        rA1 = okA ? *reinterpret_cast<const float4*>(A + (size_t)(dA + 1) * HW + l0 + m0A)
                  : make_float4(0.f, 0.f, 0.f, 0.f);
        if (doB) {
            const int dB = c * 16 + kpB * 2;
            rB0 = okB ? *reinterpret_cast<const float4*>(B + (size_t)dB * HW + s0 + m0B)
                      : make_float4(0.f, 0.f, 0.f, 0.f);
            rB1 = okB ? *reinterpret_cast<const float4*>(B + (size_t)(dB + 1) * HW + s0 + m0B)
                      : make_float4(0.f, 0.f, 0.f, 0.f);
        }
    };
    auto cvt_sts = [&](int st) {
        {
            __half2 h0 = __floats2half2_rn(rA0.x, rA1.x);
            __half2 h1 = __floats2half2_rn(rA0.y, rA1.y);
            __half2 h2 = __floats2half2_rn(rA0.z, rA1.z);
            __half2 h3 = __floats2half2_rn(rA0.w, rA1.w);
            float2 b0 = __half22float2(h0), b1 = __half22float2(h1);
            float2 b2 = __half22float2(h2), b3 = __half22float2(h3);
            __half2 L0 = __floats2half2_rn(rA0.x - b0.x, rA1.x - b0.y);
            __half2 L1 = __floats2half2_rn(rA0.y - b1.x, rA1.y - b1.y);
            __half2 L2 = __floats2half2_rn(rA0.z - b2.x, rA1.z - b2.y);
            __half2 L3 = __floats2half2_rn(rA0.w - b3.x, rA1.w - b3.y);
            *reinterpret_cast<uint4*>(&Ah[st][kpA][m0A]) = make_uint4(h2u(h0), h2u(h1), h2u(h2), h2u(h3));
            *reinterpret_cast<uint4*>(&Al[st][kpA][m0A]) = make_uint4(h2u(L0), h2u(L1), h2u(L2), h2u(L3));
        }
        if (doB) {
            __half2 h0 = __floats2half2_rn(rB0.x, rB1.x);
            __half2 h1 = __floats2half2_rn(rB0.y, rB1.y);
            __half2 h2 = __floats2half2_rn(rB0.z, rB1.z);
            __half2 h3 = __floats2half2_rn(rB0.w, rB1.w);
            float2 b0 = __half22float2(h0), b1 = __half22float2(h1);
            float2 b2 = __half22float2(h2), b3 = __half22float2(h3);
            __half2 L0 = __floats2half2_rn(rB0.x - b0.x, rB1.x - b0.y);
            __half2 L1 = __floats2half2_rn(rB0.y - b1.x, rB1.y - b1.y);
            __half2 L2 = __floats2half2_rn(rB0.z - b2.x, rB1.z - b2.y);
            __half2 L3 = __floats2half2_rn(rB0.w - b3.x, rB1.w - b3.y);
            *reinterpret_cast<uint4*>(&Bh[st][kpB][m0B]) = make_uint4(h2u(h0), h2u(h1), h2u(h2), h2u(h3));
            *reinterpret_cast<uint4*>(&Bl[st][kpB][m0B]) = make_uint4(h2u(L0), h2u(L1), h2u(L2), h2u(L3));
        }
    };

    ldg_chunk(0);
    cvt_sts(0);
    ldg_chunk(1);
    __syncthreads();

#pragma unroll
    for (int c = 0; c < 8; c++) {
        const int st = c & 1;
        unsigned ah[2][4], al[2][4], bh[4][2], bl[4][2];
#pragma unroll
        for (int mi = 0; mi < 2; mi++) {
            const int mp = rb + mi * 16 + g;
            ah[mi][0] = h2u(Ah[st][tig][mp]);
            ah[mi][1] = h2u(Ah[st][tig][mp + 8]);
            ah[mi][2] = h2u(Ah[st][tig + 4][mp]);
            ah[mi][3] = h2u(Ah[st][tig + 4][mp + 8]);
            al[mi][0] = h2u(Al[st][tig][mp]);
            al[mi][1] = h2u(Al[st][tig][mp + 8]);
            al[mi][2] = h2u(Al[st][tig + 4][mp]);
            al[mi][3] = h2u(Al[st][tig + 4][mp + 8]);
        }
#pragma unroll
        for (int ni = 0; ni < 4; ni++) {
            const int np = cb + ni * 8 + g;
            bh[ni][0] = h2u(Bh[st][tig][np]);
            bh[ni][1] = h2u(Bh[st][tig + 4][np]);
            bl[ni][0] = h2u(Bl[st][tig][np]);
            bl[ni][1] = h2u(Bl[st][tig + 4][np]);
        }
        if (c < 7) cvt_sts(st ^ 1);
        if (c < 6) ldg_chunk(c + 2);

#pragma unroll
        for (int mi = 0; mi < 2; mi++)
#pragma unroll
            for (int ni = 0; ni < 4; ni++)
                mma_f16(acc[mi][ni], ah[mi], bl[ni]);
#pragma unroll
        for (int mi = 0; mi < 2; mi++)
#pragma unroll
            for (int ni = 0; ni < 4; ni++)
                mma_f16(acc[mi][ni], al[mi], bh[ni]);
#pragma unroll
        for (int mi = 0; mi < 2; mi++)
#pragma unroll
            for (int ni = 0; ni < 4; ni++)
                mma_f16(acc[mi][ni], ah[mi], bh[ni]);

        __syncthreads();
    }

    const float inv = 1.0f / 12.8f;
    float rsum[2][2], rmax[2][2], csum[4][2];
#pragma unroll
    for (int i = 0; i < 2; i++)
#pragma unroll
        for (int r = 0; r < 2; r++) { rsum[i][r] = 0.0f; rmax[i][r] = -CUDART_INF_F; }
#pragma unroll
    for (int i = 0; i < 4; i++) { csum[i][0] = 0.0f; csum[i][1] = 0.0f; }

#pragma unroll
    for (int mi = 0; mi < 2; mi++) {
        const int row0 = l0 + rb + mi * 16 + g;
        const int row1 = row0 + 8;
        const bool rv0 = row0 < HW, rv1 = row1 < HW;
        float* orow0 = g_sm + ((size_t)(n * HW + row0)) * HW;
        float* orow1 = g_sm + ((size_t)(n * HW + row1)) * HW;
#pragma unroll
        for (int ni = 0; ni < 4; ni++) {
            const int sc0 = s0 + cb + ni * 8 + tig * 2;
            const bool cv0 = sc0 < HW, cv1 = (sc0 + 1) < HW;
            float v0 = acc[mi][ni][0] * inv;
            float v1 = acc[mi][ni][1] * inv;
            float v2 = acc[mi][ni][2] * inv;
            float v3 = acc[mi][ni][3] * inv;
            if (rv0 && cv0) *reinterpret_cast<float2*>(orow0 + sc0) = make_float2(v0, v1);
            if (rv1 && cv0) *reinterpret_cast<float2*>(orow1 + sc0) = make_float2(v2, v3);
            float e0 = cv0 ? __expf(v0) : 0.0f;
            float e1 = cv1 ? __expf(v1) : 0.0f;
            float e2 = cv0 ? __expf(v2) : 0.0f;
            float e3 = cv1 ? __expf(v3) : 0.0f;
            rsum[mi][0] += e0 + e1;
            rsum[mi][1] += e2 + e3;
            rmax[mi][0] = fmaxf(rmax[mi][0], fmaxf(cv0 ? v0 : -CUDART_INF_F, cv1 ? v1 : -CUDART_INF_F));
            rmax[mi][1] = fmaxf(rmax[mi][1], fmaxf(cv0 ? v2 : -CUDART_INF_F, cv1 ? v3 : -CUDART_INF_F));
            csum[ni][0] += (rv0 ? e0 : 0.0f) + (rv1 ? e2 : 0.0f);
            csum[ni][1] += (rv0 ? e1 : 0.0f) + (rv1 ? e3 : 0.0f);
        }
    }

#pragma unroll
    for (int m = 1; m < 4; m <<= 1) {
#pragma unroll
        for (int mi = 0; mi < 2; mi++)
#pragma unroll
            for (int r = 0; r < 2; r++) {
                rsum[mi][r] += __shfl_xor_sync(0xffffffffu, rsum[mi][r], m);
                rmax[mi][r] = fmaxf(rmax[mi][r], __shfl_xor_sync(0xffffffffu, rmax[mi][r], m));
            }
    }
    if (tig == 0) {
#pragma unroll
        for (int mi = 0; mi < 2; mi++) {
            const int rr = rb + mi * 16 + g;
            s_rs[wn][rr] = rsum[mi][0];
            s_rs[wn][rr + 8] = rsum[mi][1];
            s_rm[wn][rr] = rmax[mi][0];
            s_rm[wn][rr + 8] = rmax[mi][1];
        }
    }
#pragma unroll
    for (int m = 4; m < 32; m <<= 1) {
#pragma unroll
        for (int ni = 0; ni < 4; ni++)
#pragma unroll
            for (int q = 0; q < 2; q++)
                csum[ni][q] += __shfl_xor_sync(0xffffffffu, csum[ni][q], m);
    }
    if (g == 0) {
#pragma unroll
        for (int ni = 0; ni < 4; ni++) {
            s_cs[wm][cb + ni * 8 + tig * 2]     = csum[ni][0];
            s_cs[wm][cb + ni * 8 + tig * 2 + 1] = csum[ni][1];
        }
    }
    __syncthreads();
    if (tid < 128 && l0 + tid < HW) {
        float rs = s_rs[0][tid] + s_rs[1][tid];
        float rm = fmaxf(s_rm[0][tid], s_rm[1][tid]);
        g_rp[(n * NBXS + blockIdx.x) * HW + l0 + tid] = rs;
        g_vp[(n * NBXS + blockIdx.x) * HW + l0 + tid] = rm;
    }
    if (tid < 64 && s0 + tid < HW) {
        float cs = s_cs[0][tid] + s_cs[1][tid] + s_cs[2][tid] + s_cs[3][tid];
        g_cp[(n * NBY + blockIdx.y) * HW + s0 + tid] = cs;
    }
}

// ---------------- colfin ----------------
__global__ __launch_bounds__(256) void colfin_kernel(int n) {
    const int s = blockIdx.x * 256 + threadIdx.x;
    __shared__ float mn[256], mx[256];
    float v = CUDART_INF_F;
    float hi = -CUDART_INF_F;
    if (s < HW) {
        float acc = 0.0f;
#pragma unroll
        for (int b = 0; b < NBY; b++) acc += g_cp[(n * NBY + b) * HW + s];
        v = logf(acc);
        g_LC[n * HW + s] = v;
        hi = v;
    }
    const int tid = threadIdx.x;
    mn[tid] = v; mx[tid] = hi;
    __syncthreads();
    for (int o = 64; o > 0; o >>= 1) {
        if ((tid & 127) < o) mn[tid] = fminf(mn[tid], mn[tid + o]);
        __syncthreads();
    }
    if ((tid & 127) == 0) {
        int blk = (blockIdx.x * 256 + tid) >> 7;
        if (blk < NBX) g_lcmin_blk[n * NBX + blk] = mn[tid];
    }
    for (int o = 128; o > 0; o >>= 1) {
        if (tid < o) mx[tid] = fmaxf(mx[tid], mx[tid + o]);
        __syncthreads();
    }
    if (tid == 0) g_lcmax_part[n * LCPARTS + blockIdx.x] = mx[0];
}

// ---------------- rowfin ----------------
__global__ __launch_bounds__(256) void rowfin_kernel(int n) {
    const int l = blockIdx.x * 256 + threadIdx.x;
    __shared__ float lcb[NBX];
    if (threadIdx.x < NBX) lcb[threadIdx.x] = g_lcmin_blk[n * NBX + threadIdx.x];
    __syncthreads();
    if (l >= HW) return;
    float s = 0.0f, m = -CUDART_INF_F, rbnd = -CUDART_INF_F;
#pragma unroll
    for (int b = 0; b < NBXS; b++) {
        float vp = g_vp[(n * NBXS + b) * HW + l];
        s += g_rp[(n * NBXS + b) * HW + l];
        m = fmaxf(m, vp);
        rbnd = fmaxf(rbnd, fmaf(2.0f, vp, -lcb[b >> 1]));
    }
    float LR = logf(s);
    g_LR[n * HW + l] = LR;
    g_vmax[n * HW + l] = m;
    g_rowbound[n * HW + l] = rbnd - LR;
}

// ---------------- threshold + row compaction ----------------
__global__ __launch_bounds__(1024) void bound_kernel(int n) {
    const int tid = threadIdx.x;
    __shared__ float Lbuf[HW];
    __shared__ float red1[1024], red2[1024];
    __shared__ int hist[2048];
    __shared__ unsigned ssum[1024];
    __shared__ float s_lmn, s_lmx, s_lcmax, s_t;

    // parallel lcmax fold
    {
        float v = (tid < LCPARTS) ? g_lcmax_part[n * LCPARTS + tid] : -CUDART_INF_F;
        red1[tid] = v;
        __syncthreads();
        for (int o = 16; o > 0; o >>= 1) {
            if (tid < o) red1[tid] = fmaxf(red1[tid], red1[tid + o]);
            __syncthreads();
        }
        if (tid == 0) {
            s_lcmax = red1[0];
            g_cnt[n] = 0;
            g_rowcnt[n] = 0;
        }
    }
    __syncthreads();
    const float lcmax = s_lcmax;

    float lmn = CUDART_INF_F, lmx = -CUDART_INF_F;
    for (int l = tid; l < HW; l += 1024) {
        float L = fmaf(2.0f, g_vmax[n * HW + l], -g_LR[n * HW + l]) - lcmax;
        Lbuf[l] = L;
        lmn = fminf(lmn, L); lmx = fmaxf(lmx, L);
    }
    red1[tid] = lmn; red2[tid] = lmx;
    __syncthreads();
    for (int o = 512; o > 0; o >>= 1) {
        if (tid < o) {
            red1[tid] = fminf(red1[tid], red1[tid + o]);
            red2[tid] = fmaxf(red2[tid], red2[tid + o]);
        }
        __syncthreads();
    }
    if (tid == 0) { s_lmn = red1[0]; s_lmx = red2[0]; }
    __syncthreads();
    const float Lmn = s_lmn;
    const float binw = (s_lmx - Lmn) * (1.0f / 2048.0f);

    if (binw < 1e-30f) {
        if (tid == 0) s_t = Lmn;
    } else {
        for (int i = tid; i < 2048; i += 1024) hist[i] = 0;
        __syncthreads();
        for (int l = tid; l < HW; l += 1024) {
            int b = (int)((Lbuf[l] - Lmn) / binw);
            b = max(0, min(2047, b));
            atomicAdd(&hist[b], 1);
        }
        __syncthreads();
        unsigned csum = (unsigned)hist[tid * 2] + (unsigned)hist[tid * 2 + 1];
        ssum[tid] = csum;
        __syncthreads();
        for (int off = 1; off < 1024; off <<= 1) {
            unsigned v = (tid + off < 1024) ? ssum[tid + off] : 0u;
            __syncthreads();
            ssum[tid] += v;
            __syncthreads();
        }
        unsigned mine = ssum[tid];
        unsigned nxt = (tid < 1023) ? ssum[tid + 1] : 0u;
        if (mine >= KTOP && nxt < KTOP) {
            unsigned cum = nxt;
            int b = tid * 2 + 1;
            for (; b > tid * 2; b--) {
                cum += (unsigned)hist[b];
                if (cum >= KTOP) break;
            }
            s_t = Lmn + (float)(b - 1) * binw;
        }
    }
    __syncthreads();
    const float t = s_t;
    if (tid == 0) g_thrv[n] = t;
    for (int l = tid; l < HW; l += 1024) {
        if (g_rowbound[n * HW + l] >= t) {
            int p = atomicAdd(&g_rowcnt[n], 1);
            g_rowlist[n * HW + p] = l;
        }
    }
}

// ---------------- collect ----------------
__global__ __launch_bounds__(128) void collect_kernel(int n) {
    const float t = g_thrv[n];
    const int rcnt = g_rowcnt[n];
    const int tid = threadIdx.x;
    __shared__ unsigned s_mask;
    const float* LC = g_LC + n * HW;

    for (int ri = blockIdx.x; ri < rcnt; ri += gridDim.x) {
        const int l = g_rowlist[n * HW + ri];
        const float LR = g_LR[n * HW + l];
        if (tid < 32) {
            bool flag = false;
            if (tid < NBX) {
                float vp = g_vp[(n * NBXS + 2 * tid) * HW + l];
                if (2 * tid + 1 < NBXS)
                    vp = fmaxf(vp, g_vp[(n * NBXS + 2 * tid + 1) * HW + l]);
                flag = (fmaf(2.0f, vp, -LR) - g_lcmin_blk[n * NBX + tid]) >= t;
            }
            unsigned m = __ballot_sync(0xffffffffu, flag);
            if (tid == 0) s_mask = m;
        }
        __syncthreads();
        unsigned mask = s_mask;
        const float* row = g_sm + ((size_t)(n * HW + l)) * HW;
        while (mask) {
            int b = __ffs(mask) - 1;
            mask &= mask - 1;
            int s = b * 128 + tid;
            if (s < HW) {
                float sc = fmaf(2.0f, row[s], -LR) - LC[s];
                if (sc >= t) {
                    int p = atomicAdd(&g_cnt[n], 1);
                    if (p < CAP) {
                        g_cv[n * CAP + p] = sc;
                        g_ci[n * CAP + p] = l * HW + s;
                    }
                }
            }
        }
        __syncthreads();
    }
}

// ---------------- select ----------------
__global__ __launch_bounds__(256) void select_kernel(int n) {
    const int tid = threadIdx.x;
    int cnt = g_cnt[n];
    if (cnt > CAP) cnt = CAP;
    float* cv = g_cv + n * CAP;
    int* ci = g_ci + n * CAP;

    if (cnt <= 2048) {
        __shared__ unsigned long long key[2048];
        for (int i = tid; i < 2048; i += 256) {
            unsigned long long k = 0ull;
            if (i < cnt)
                k = ((unsigned long long)mono_bits(cv[i]) << 32) |
                    (unsigned long long)(0xFFFFFFFFu - (unsigned)ci[i]);
            key[i] = k;
        }
        __syncthreads();
        for (int kk = 2; kk <= 2048; kk <<= 1) {
            for (int j = kk >> 1; j > 0; j >>= 1) {
                for (int i = tid; i < 2048; i += 256) {
                    int ixj = i ^ j;
                    if (ixj > i) {
                        bool dirDesc = ((i & kk) == 0);
                        unsigned long long a = key[i], b = key[ixj];
                        if ((a < b) == dirDesc) { key[i] = b; key[ixj] = a; }
                    }
                }
                __syncthreads();
            }
        }
        if (tid < KTOP)
            g_topi[n * KTOP + tid] = (int)(0xFFFFFFFFu - (unsigned)(key[tid] & 0xFFFFFFFFull));
        return;
    }

    __shared__ float sv[256];
    __shared__ int si[256];
    __shared__ int sp[256];
    for (int k = 0; k < KTOP; k++) {
        float bv = -CUDART_INF_F; int bi = 0x7FFFFFFF; int bp = -1;
        for (int j = tid; j < cnt; j += 256) {
            float v = cv[j]; int idx = ci[j];
            if (v > bv || (v == bv && idx < bi)) { bv = v; bi = idx; bp = j; }
        }
        sv[tid] = bv; si[tid] = bi; sp[tid] = bp;
        __syncthreads();
        for (int o = 128; o > 0; o >>= 1) {
            if (tid < o) {
                if (sv[tid + o] > sv[tid] || (sv[tid + o] == sv[tid] && si[tid + o] < si[tid])) {
                    sv[tid] = sv[tid + o]; si[tid] = si[tid + o]; sp[tid] = sp[tid + o];
                }
            }
            __syncthreads();
        }
        if (tid == 0) {
            g_topi[n * KTOP + k] = si[0];
            if (sp[0] >= 0) cv[sp[0]] = -CUDART_INF_F;
        }
        __syncthreads();
    }
}

// ---------------- final (prep fused), per batch: np = n + 4*blockIdx.y ----------------
__global__ __launch_bounds__(256) void final_kernel(const float* __restrict__ x,
                                                    const float* __restrict__ W,
                                                    const float* __restrict__ bvec,
                                                    float* __restrict__ out, int n) {
    const int d = blockIdx.x;
    const int np = n + 4 * blockIdx.y;
    const bool side1 = (np >= 4);
    const int tid = threadIdx.x;

    __shared__ float rS[128], rX[128], rY[128];
    __shared__ float s_e, s_wx, s_wy;
    if (tid < 128) {
        float pS = 0.0f, px = 0.0f, py = 0.0f;
        if (tid < KTOP) {
            int idx = g_topi[n * KTOP + tid];
            int r = side1 ? (idx % HW) : (idx / HW);
            float cx = (float)(r % WDIM) / 60.0f;
            float cy = (float)(r / WDIM) / 60.0f;
            float w0 = W[d * (2 * KTOP) + 2 * tid];
            float w1 = W[d * (2 * KTOP) + 2 * tid + 1];
            pS = fmaf(w0, cx, w1 * cy);
            px = w0; py = w1;
        }
        rS[tid] = pS; rX[tid] = px; rY[tid] = py;
    }
    __syncthreads();
    for (int o = 64; o > 0; o >>= 1) {
        if (tid < o) {
            rS[tid] += rS[tid + o];
            rX[tid] += rX[tid + o];
            rY[tid] += rY[tid + o];
        }
        __syncthreads();
    }
    if (tid == 0) {
        s_e = -rS[0] + bvec[d];
        s_wx = rX[0];
        s_wy = rY[0];
    }
    __syncthreads();
    const float wx = s_wx, wy = s_wy, e = s_e;
    const size_t base = ((size_t)np * CCH + d) * HW;
    for (int p = tid; p < HW; p += 256) {
        float gx = (float)(p % WDIM) / 60.0f;
        float gy = (float)(p / WDIM) / 60.0f;
        out[base + p] = x[base + p] + gx * wx + gy * wy + e;
    }
}

// ---------------- launch: per-batch fork/join overlap ----------------
extern "C" void kernel_launch(void* const* d_in, const int* in_sizes, int n_in,
                              void* d_out, int out_size) {
    (void)in_sizes; (void)n_in; (void)out_size;
    const float* x = (const float*)d_in[0];
    const float* W = (const float*)d_in[1];
    const float* b = (const float*)d_in[2];
    float* out = (float*)d_out;

    static cudaStream_t s2 = nullptr;
    static cudaEvent_t evG[NBATCH];
    static cudaEvent_t evEnd;
    if (s2 == nullptr) {
        cudaStreamCreateWithFlags(&s2, cudaStreamNonBlocking);
        for (int i = 0; i < NBATCH; i++)
            cudaEventCreateWithFlags(&evG[i], cudaEventDisableTiming);
        cudaEventCreateWithFlags(&evEnd, cudaEventDisableTiming);
    }

    for (int n = 0; n < NBATCH; n++) {
        gemm_kernel<<<dim3(NBXS, NBY), 256>>>(x, n);
        cudaEventRecord(evG[n], 0);
        cudaStreamWaitEvent(s2, evG[n], 0);
        colfin_kernel<<<LCPARTS, 256, 0, s2>>>(n);
        rowfin_kernel<<<LCPARTS, 256, 0, s2>>>(n);
        bound_kernel<<<1, 1024, 0, s2>>>(n);
        collect_kernel<<<64, 128, 0, s2>>>(n);
        select_kernel<<<1, 256, 0, s2>>>(n);
        final_kernel<<<dim3(CCH, 2), 256, 0, s2>>>(x, W, b, out, n);
    }
    cudaEventRecord(evEnd, s2);
    cudaStreamWaitEvent(0, evEnd, 0);
}

// round 16
// speedup vs baseline: 1.8000x; 1.8000x over previous
#include <cuda_runtime.h>
#include <cuda_fp16.h>
#include <math_constants.h>
#include <stdint.h>

#define HW    3600
#define WDIM  60
#define CCH   128
#define NBATCH 4
#define KTOP  100
#define CAP   65536
#define NBY   29
#define NBXS  57
#define NBX   29
#define LCPARTS 15
#define SPH   136
#define SPHB  72

// ---------------- device scratch ----------------
__device__ float g_sm[(size_t)NBATCH * HW * HW];
__device__ float g_rp[NBATCH * NBXS * HW];
__device__ float g_cp[NBATCH * NBY * HW];
__device__ float g_vp[NBATCH * NBXS * HW];
__device__ float g_LR[NBATCH * HW];
__device__ float g_LC[NBATCH * HW];
__device__ float g_vmax[NBATCH * HW];
__device__ float g_rowbound[NBATCH * HW];
__device__ float g_lcmin_blk[NBATCH * NBX];
__device__ float g_lcmax_part[NBATCH * LCPARTS];
__device__ float g_thrv[NBATCH];
__device__ int   g_cnt[NBATCH];
__device__ int   g_rowcnt[NBATCH];
__device__ int   g_rowlist[NBATCH * HW];
__device__ float g_cv[NBATCH * CAP];
__device__ int   g_ci[NBATCH * CAP];
__device__ int   g_topi[NBATCH * KTOP];

// ---------------- helpers ----------------
__device__ __forceinline__ void mma_f16(float c[4], const unsigned a[4], const unsigned b[2]) {
    asm volatile(
        "mma.sync.aligned.m16n8k16.row.col.f32.f16.f16.f32 "
        "{%0,%1,%2,%3}, {%4,%5,%6,%7}, {%8,%9}, {%0,%1,%2,%3};"
        : "+f"(c[0]), "+f"(c[1]), "+f"(c[2]), "+f"(c[3])
        : "r"(a[0]), "r"(a[1]), "r"(a[2]), "r"(a[3]), "r"(b[0]), "r"(b[1]));
}
__device__ __forceinline__ unsigned mono_bits(float f) {
    unsigned b = __float_as_uint(f);
    return (b & 0x80000000u) ? ~b : (b | 0x80000000u);
}
__device__ __forceinline__ unsigned h2u(__half2 h) {
    return *reinterpret_cast<unsigned*>(&h);
}

// ---------------- GEMM: fp16 x3 split, 128x64 tile, 256 thr, 2 CTA/SM ----------------
__global__ __launch_bounds__(256, 2) void gemm_kernel(const float* __restrict__ x) {
    __shared__ __align__(16) __half2 Ah[2][8][SPH];
    __shared__ __align__(16) __half2 Al[2][8][SPH];
    __shared__ __align__(16) __half2 Bh[2][8][SPHB];
    __shared__ __align__(16) __half2 Bl[2][8][SPHB];
    __shared__ float s_rs[2][128];
    __shared__ float s_rm[2][128];
    __shared__ float s_cs[4][64];

    const int n  = blockIdx.z;
    const int l0 = blockIdx.y * 128;
    const int s0 = blockIdx.x * 64;
    const float* A = x + (size_t)n * CCH * HW;
    const float* B = x + (size_t)(n + NBATCH) * CCH * HW;
    const int tid = threadIdx.x;
    const int lane = tid & 31;
    const int wid = tid >> 5;
    const int g = lane >> 2, tig = lane & 3;
    const int wm = wid & 3, wn = wid >> 2;
    const int rb = wm * 32, cb = wn * 32;

    const int kpA = tid >> 5;
    const int m0A = (lane) << 2;
    const bool okA = (l0 + m0A) < HW;
    const int kpB = (tid & 127) >> 4;
    const int m0B = (tid & 15) << 2;
    const bool doB = tid < 128;
    const bool okB = (s0 + m0B) < HW;

    float acc[2][4][4];
#pragma unroll
    for (int mi = 0; mi < 2; mi++)
#pragma unroll
        for (int ni = 0; ni < 4; ni++)
#pragma unroll
            for (int q = 0; q < 4; q++) acc[mi][ni][q] = 0.0f;

    float4 rA0, rA1, rB0, rB1;

    auto ldg_chunk = [&](int c) {
        const int dA = c * 16 + kpA * 2;
        rA0 = okA ? *reinterpret_cast<const float4*>(A + (size_t)dA * HW + l0 + m0A)
                  : make_float4(0.f, 0.f, 0.f, 0.f);
        rA1 = okA ? *reinterpret_cast<const float4*>(A + (size_t)(dA + 1) * HW + l0 + m0A)
                  : make_float4(0.f, 0.f, 0.f, 0.f);
        if (doB) {
            const int dB = c * 16 + kpB * 2;
            rB0 = okB ? *reinterpret_cast<const float4*>(B + (size_t)dB * HW + s0 + m0B)
                      : make_float4(0.f, 0.f, 0.f, 0.f);
            rB1 = okB ? *reinterpret_cast<const float4*>(B + (size_t)(dB + 1) * HW + s0 + m0B)
                      : make_float4(0.f, 0.f, 0.f, 0.f);
        }
    };
    auto cvt_sts = [&](int st) {
        {
            __half2 h0 = __floats2half2_rn(rA0.x, rA1.x);
            __half2 h1 = __floats2half2_rn(rA0.y, rA1.y);
            __half2 h2 = __floats2half2_rn(rA0.z, rA1.z);
            __half2 h3 = __floats2half2_rn(rA0.w, rA1.w);
            float2 b0 = __half22float2(h0), b1 = __half22float2(h1);
            float2 b2 = __half22float2(h2), b3 = __half22float2(h3);
            __half2 L0 = __floats2half2_rn(rA0.x - b0.x, rA1.x - b0.y);
            __half2 L1 = __floats2half2_rn(rA0.y - b1.x, rA1.y - b1.y);
            __half2 L2 = __floats2half2_rn(rA0.z - b2.x, rA1.z - b2.y);
            __half2 L3 = __floats2half2_rn(rA0.w - b3.x, rA1.w - b3.y);
            *reinterpret_cast<uint4*>(&Ah[st][kpA][m0A]) = make_uint4(h2u(h0), h2u(h1), h2u(h2), h2u(h3));
            *reinterpret_cast<uint4*>(&Al[st][kpA][m0A]) = make_uint4(h2u(L0), h2u(L1), h2u(L2), h2u(L3));
        }
        if (doB) {
            __half2 h0 = __floats2half2_rn(rB0.x, rB1.x);
            __half2 h1 = __floats2half2_rn(rB0.y, rB1.y);
            __half2 h2 = __floats2half2_rn(rB0.z, rB1.z);
            __half2 h3 = __floats2half2_rn(rB0.w, rB1.w);
            float2 b0 = __half22float2(h0), b1 = __half22float2(h1);
            float2 b2 = __half22float2(h2), b3 = __half22float2(h3);
            __half2 L0 = __floats2half2_rn(rB0.x - b0.x, rB1.x - b0.y);
            __half2 L1 = __floats2half2_rn(rB0.y - b1.x, rB1.y - b1.y);
            __half2 L2 = __floats2half2_rn(rB0.z - b2.x, rB1.z - b2.y);
            __half2 L3 = __floats2half2_rn(rB0.w - b3.x, rB1.w - b3.y);
            *reinterpret_cast<uint4*>(&Bh[st][kpB][m0B]) = make_uint4(h2u(h0), h2u(h1), h2u(h2), h2u(h3));
            *reinterpret_cast<uint4*>(&Bl[st][kpB][m0B]) = make_uint4(h2u(L0), h2u(L1), h2u(L2), h2u(L3));
        }
    };

    ldg_chunk(0);
    cvt_sts(0);
    ldg_chunk(1);
    __syncthreads();

#pragma unroll
    for (int c = 0; c < 8; c++) {
        const int st = c & 1;
        unsigned ah[2][4], al[2][4], bh[4][2], bl[4][2];
#pragma unroll
        for (int mi = 0; mi < 2; mi++) {
            const int mp = rb + mi * 16 + g;
            ah[mi][0] = h2u(Ah[st][tig][mp]);
            ah[mi][1] = h2u(Ah[st][tig][mp + 8]);
            ah[mi][2] = h2u(Ah[st][tig + 4][mp]);
            ah[mi][3] = h2u(Ah[st][tig + 4][mp + 8]);
            al[mi][0] = h2u(Al[st][tig][mp]);
            al[mi][1] = h2u(Al[st][tig][mp + 8]);
            al[mi][2] = h2u(Al[st][tig + 4][mp]);
            al[mi][3] = h2u(Al[st][tig + 4][mp + 8]);
        }
#pragma unroll
        for (int ni = 0; ni < 4; ni++) {
            const int np = cb + ni * 8 + g;
            bh[ni][0] = h2u(Bh[st][tig][np]);
            bh[ni][1] = h2u(Bh[st][tig + 4][np]);
            bl[ni][0] = h2u(Bl[st][tig][np]);
            bl[ni][1] = h2u(Bl[st][tig + 4][np]);
        }
        if (c < 7) cvt_sts(st ^ 1);
        if (c < 6) ldg_chunk(c + 2);

#pragma unroll
        for (int mi = 0; mi < 2; mi++)
#pragma unroll
            for (int ni = 0; ni < 4; ni++)
                mma_f16(acc[mi][ni], ah[mi], bl[ni]);
#pragma unroll
        for (int mi = 0; mi < 2; mi++)
#pragma unroll
            for (int ni = 0; ni < 4; ni++)
                mma_f16(acc[mi][ni], al[mi], bh[ni]);
#pragma unroll
        for (int mi = 0; mi < 2; mi++)
#pragma unroll
            for (int ni = 0; ni < 4; ni++)
                mma_f16(acc[mi][ni], ah[mi], bh[ni]);

        __syncthreads();
    }

    const float inv = 1.0f / 12.8f;
    float rsum[2][2], rmax[2][2], csum[4][2];
#pragma unroll
    for (int i = 0; i < 2; i++)
#pragma unroll
        for (int r = 0; r < 2; r++) { rsum[i][r] = 0.0f; rmax[i][r] = -CUDART_INF_F; }
#pragma unroll
    for (int i = 0; i < 4; i++) { csum[i][0] = 0.0f; csum[i][1] = 0.0f; }

#pragma unroll
    for (int mi = 0; mi < 2; mi++) {
        const int row0 = l0 + rb + mi * 16 + g;
        const int row1 = row0 + 8;
        const bool rv0 = row0 < HW, rv1 = row1 < HW;
        float* orow0 = g_sm + ((size_t)(n * HW + row0)) * HW;
        float* orow1 = g_sm + ((size_t)(n * HW + row1)) * HW;
#pragma unroll
        for (int ni = 0; ni < 4; ni++) {
            const int sc0 = s0 + cb + ni * 8 + tig * 2;
            const bool cv0 = sc0 < HW, cv1 = (sc0 + 1) < HW;
            float v0 = acc[mi][ni][0] * inv;
            float v1 = acc[mi][ni][1] * inv;
            float v2 = acc[mi][ni][2] * inv;
            float v3 = acc[mi][ni][3] * inv;
            if (rv0 && cv0) *reinterpret_cast<float2*>(orow0 + sc0) = make_float2(v0, v1);
            if (rv1 && cv0) *reinterpret_cast<float2*>(orow1 + sc0) = make_float2(v2, v3);
            float e0 = cv0 ? __expf(v0) : 0.0f;
            float e1 = cv1 ? __expf(v1) : 0.0f;
            float e2 = cv0 ? __expf(v2) : 0.0f;
            float e3 = cv1 ? __expf(v3) : 0.0f;
            rsum[mi][0] += e0 + e1;
            rsum[mi][1] += e2 + e3;
            rmax[mi][0] = fmaxf(rmax[mi][0], fmaxf(cv0 ? v0 : -CUDART_INF_F, cv1 ? v1 : -CUDART_INF_F));
            rmax[mi][1] = fmaxf(rmax[mi][1], fmaxf(cv0 ? v2 : -CUDART_INF_F, cv1 ? v3 : -CUDART_INF_F));
            csum[ni][0] += (rv0 ? e0 : 0.0f) + (rv1 ? e2 : 0.0f);
            csum[ni][1] += (rv0 ? e1 : 0.0f) + (rv1 ? e3 : 0.0f);
        }
    }

#pragma unroll
    for (int m = 1; m < 4; m <<= 1) {
#pragma unroll
        for (int mi = 0; mi < 2; mi++)
#pragma unroll
            for (int r = 0; r < 2; r++) {
                rsum[mi][r] += __shfl_xor_sync(0xffffffffu, rsum[mi][r], m);
                rmax[mi][r] = fmaxf(rmax[mi][r], __shfl_xor_sync(0xffffffffu, rmax[mi][r], m));
            }
    }
    if (tig == 0) {
#pragma unroll
        for (int mi = 0; mi < 2; mi++) {
            const int rr = rb + mi * 16 + g;
            s_rs[wn][rr] = rsum[mi][0];
            s_rs[wn][rr + 8] = rsum[mi][1];
            s_rm[wn][rr] = rmax[mi][0];
            s_rm[wn][rr + 8] = rmax[mi][1];
        }
    }
#pragma unroll
    for (int m = 4; m < 32; m <<= 1) {
#pragma unroll
        for (int ni = 0; ni < 4; ni++)
#pragma unroll
            for (int q = 0; q < 2; q++)
                csum[ni][q] += __shfl_xor_sync(0xffffffffu, csum[ni][q], m);
    }
    if (g == 0) {
#pragma unroll
        for (int ni = 0; ni < 4; ni++) {
            s_cs[wm][cb + ni * 8 + tig * 2]     = csum[ni][0];
            s_cs[wm][cb + ni * 8 + tig * 2 + 1] = csum[ni][1];
        }
    }
    __syncthreads();
    if (tid < 128 && l0 + tid < HW) {
        float rs = s_rs[0][tid] + s_rs[1][tid];
        float rm = fmaxf(s_rm[0][tid], s_rm[1][tid]);
        g_rp[(n * NBXS + blockIdx.x) * HW + l0 + tid] = rs;
        g_vp[(n * NBXS + blockIdx.x) * HW + l0 + tid] = rm;
    }
    if (tid < 64 && s0 + tid < HW) {
        float cs = s_cs[0][tid] + s_cs[1][tid] + s_cs[2][tid] + s_cs[3][tid];
        g_cp[(n * NBY + blockIdx.y) * HW + s0 + tid] = cs;
    }
}

// ---------------- colfin ----------------
__global__ __launch_bounds__(256) void colfin_kernel() {
    const int n = blockIdx.y;
    const int s = blockIdx.x * 256 + threadIdx.x;
    __shared__ float mn[256], mx[256];
    float v = CUDART_INF_F;
    float hi = -CUDART_INF_F;
    if (s < HW) {
        float acc = 0.0f;
#pragma unroll
        for (int b = 0; b < NBY; b++) acc += g_cp[(n * NBY + b) * HW + s];
        v = logf(acc);
        g_LC[n * HW + s] = v;
        hi = v;
    }
    const int tid = threadIdx.x;
    mn[tid] = v; mx[tid] = hi;
    __syncthreads();
    for (int o = 64; o > 0; o >>= 1) {
        if ((tid & 127) < o) mn[tid] = fminf(mn[tid], mn[tid + o]);
        __syncthreads();
    }
    if ((tid & 127) == 0) {
        int blk = (blockIdx.x * 256 + tid) >> 7;
        if (blk < NBX) g_lcmin_blk[n * NBX + blk] = mn[tid];
    }
    for (int o = 128; o > 0; o >>= 1) {
        if (tid < o) mx[tid] = fmaxf(mx[tid], mx[tid + o]);
        __syncthreads();
    }
    if (tid == 0) g_lcmax_part[n * LCPARTS + blockIdx.x] = mx[0];
}

// ---------------- rowfin ----------------
__global__ __launch_bounds__(256) void rowfin_kernel() {
    const int n = blockIdx.y;
    const int l = blockIdx.x * 256 + threadIdx.x;
    __shared__ float lcb[NBX];
    if (threadIdx.x < NBX) lcb[threadIdx.x] = g_lcmin_blk[n * NBX + threadIdx.x];
    __syncthreads();
    if (l >= HW) return;
    float s = 0.0f, m = -CUDART_INF_F, rbnd = -CUDART_INF_F;
#pragma unroll
    for (int b = 0; b < NBXS; b++) {
        float vp = g_vp[(n * NBXS + b) * HW + l];
        s += g_rp[(n * NBXS + b) * HW + l];
        m = fmaxf(m, vp);
        rbnd = fmaxf(rbnd, fmaf(2.0f, vp, -lcb[b >> 1]));
    }
    float LR = logf(s);
    g_LR[n * HW + l] = LR;
    g_vmax[n * HW + l] = m;
    g_rowbound[n * HW + l] = rbnd - LR;
}

// ---------------- threshold + row compaction ----------------
__global__ __launch_bounds__(1024) void bound_kernel() {
    const int n = blockIdx.x;
    const int tid = threadIdx.x;
    __shared__ float Lbuf[HW];
    __shared__ float red1[1024], red2[1024];
    __shared__ int hist[2048];
    __shared__ unsigned ssum[1024];
    __shared__ float s_lmn, s_lmx, s_lcmax, s_t;

    // parallel lcmax fold
    {
        float v = (tid < LCPARTS) ? g_lcmax_part[n * LCPARTS + tid] : -CUDART_INF_F;
        red1[tid] = v;
        __syncthreads();
        for (int o = 16; o > 0; o >>= 1) {
            if (tid < o) red1[tid] = fmaxf(red1[tid], red1[tid + o]);
            __syncthreads();
        }
        if (tid == 0) {
            s_lcmax = red1[0];
            g_cnt[n] = 0;
            g_rowcnt[n] = 0;
        }
    }
    __syncthreads();
    const float lcmax = s_lcmax;

    float lmn = CUDART_INF_F, lmx = -CUDART_INF_F;
    for (int l = tid; l < HW; l += 1024) {
        float L = fmaf(2.0f, g_vmax[n * HW + l], -g_LR[n * HW + l]) - lcmax;
        Lbuf[l] = L;
        lmn = fminf(lmn, L); lmx = fmaxf(lmx, L);
    }
    red1[tid] = lmn; red2[tid] = lmx;
    __syncthreads();
    for (int o = 512; o > 0; o >>= 1) {
        if (tid < o) {
            red1[tid] = fminf(red1[tid], red1[tid + o]);
            red2[tid] = fmaxf(red2[tid], red2[tid + o]);
        }
        __syncthreads();
    }
    if (tid == 0) { s_lmn = red1[0]; s_lmx = red2[0]; }
    __syncthreads();
    const float Lmn = s_lmn;
    const float binw = (s_lmx - Lmn) * (1.0f / 2048.0f);

    if (binw < 1e-30f) {
        if (tid == 0) s_t = Lmn;
    } else {
        for (int i = tid; i < 2048; i += 1024) hist[i] = 0;
        __syncthreads();
        for (int l = tid; l < HW; l += 1024) {
            int b = (int)((Lbuf[l] - Lmn) / binw);
            b = max(0, min(2047, b));
            atomicAdd(&hist[b], 1);
        }
        __syncthreads();
        unsigned csum = (unsigned)hist[tid * 2] + (unsigned)hist[tid * 2 + 1];
        ssum[tid] = csum;
        __syncthreads();
        for (int off = 1; off < 1024; off <<= 1) {
            unsigned v = (tid + off < 1024) ? ssum[tid + off] : 0u;
            __syncthreads();
            ssum[tid] += v;
            __syncthreads();
        }
        unsigned mine = ssum[tid];
        unsigned nxt = (tid < 1023) ? ssum[tid + 1] : 0u;
        if (mine >= KTOP && nxt < KTOP) {
            unsigned cum = nxt;
            int b = tid * 2 + 1;
            for (; b > tid * 2; b--) {
                cum += (unsigned)hist[b];
                if (cum >= KTOP) break;
            }
            s_t = Lmn + (float)(b - 1) * binw;
        }
    }
    __syncthreads();
    const float t = s_t;
    if (tid == 0) g_thrv[n] = t;
    for (int l = tid; l < HW; l += 1024) {
        if (g_rowbound[n * HW + l] >= t) {
            int p = atomicAdd(&g_rowcnt[n], 1);
            g_rowlist[n * HW + p] = l;
        }
    }
}

// ---------------- collect ----------------
__global__ __launch_bounds__(128) void collect_kernel() {
    const int n = blockIdx.y;
    const float t = g_thrv[n];
    const int rcnt = g_rowcnt[n];
    const int tid = threadIdx.x;
    __shared__ unsigned s_mask;
    const float* LC = g_LC + n * HW;

    for (int ri = blockIdx.x; ri < rcnt; ri += gridDim.x) {
        const int l = g_rowlist[n * HW + ri];
        const float LR = g_LR[n * HW + l];
        if (tid < 32) {
            bool flag = false;
            if (tid < NBX) {
                float vp = g_vp[(n * NBXS + 2 * tid) * HW + l];
                if (2 * tid + 1 < NBXS)
                    vp = fmaxf(vp, g_vp[(n * NBXS + 2 * tid + 1) * HW + l]);
                flag = (fmaf(2.0f, vp, -LR) - g_lcmin_blk[n * NBX + tid]) >= t;
            }
            unsigned m = __ballot_sync(0xffffffffu, flag);
            if (tid == 0) s_mask = m;
        }
        __syncthreads();
        unsigned mask = s_mask;
        const float* row = g_sm + ((size_t)(n * HW + l)) * HW;
        while (mask) {
            int b = __ffs(mask) - 1;
            mask &= mask - 1;
            int s = b * 128 + tid;
            if (s < HW) {
                float sc = fmaf(2.0f, row[s], -LR) - LC[s];
                if (sc >= t) {
                    int p = atomicAdd(&g_cnt[n], 1);
                    if (p < CAP) {
                        g_cv[n * CAP + p] = sc;
                        g_ci[n * CAP + p] = l * HW + s;
                    }
                }
            }
        }
        __syncthreads();
    }
}

// ---------------- select ----------------
__global__ __launch_bounds__(256) void select_kernel() {
    const int n = blockIdx.x;
    const int tid = threadIdx.x;
    int cnt = g_cnt[n];
    if (cnt > CAP) cnt = CAP;
    float* cv = g_cv + n * CAP;
    int* ci = g_ci + n * CAP;

    if (cnt <= 2048) {
        __shared__ unsigned long long key[2048];
        for (int i = tid; i < 2048; i += 256) {
            unsigned long long k = 0ull;
            if (i < cnt)
                k = ((unsigned long long)mono_bits(cv[i]) << 32) |
                    (unsigned long long)(0xFFFFFFFFu - (unsigned)ci[i]);
            key[i] = k;
        }
        __syncthreads();
        for (int kk = 2; kk <= 2048; kk <<= 1) {
            for (int j = kk >> 1; j > 0; j >>= 1) {
                for (int i = tid; i < 2048; i += 256) {
                    int ixj = i ^ j;
                    if (ixj > i) {
                        bool dirDesc = ((i & kk) == 0);
                        unsigned long long a = key[i], b = key[ixj];
                        if ((a < b) == dirDesc) { key[i] = b; key[ixj] = a; }
                    }
                }
                __syncthreads();
            }
        }
        if (tid < KTOP)
            g_topi[n * KTOP + tid] = (int)(0xFFFFFFFFu - (unsigned)(key[tid] & 0xFFFFFFFFull));
        return;
    }

    __shared__ float sv[256];
    __shared__ int si[256];
    __shared__ int sp[256];
    for (int k = 0; k < KTOP; k++) {
        float bv = -CUDART_INF_F; int bi = 0x7FFFFFFF; int bp = -1;
        for (int j = tid; j < cnt; j += 256) {
            float v = cv[j]; int idx = ci[j];
            if (v > bv || (v == bv && idx < bi)) { bv = v; bi = idx; bp = j; }
        }
        sv[tid] = bv; si[tid] = bi; sp[tid] = bp;
        __syncthreads();
        for (int o = 128; o > 0; o >>= 1) {
            if (tid < o) {
                if (sv[tid + o] > sv[tid] || (sv[tid + o] == sv[tid] && si[tid + o] < si[tid])) {
                    sv[tid] = sv[tid + o]; si[tid] = si[tid + o]; sp[tid] = sp[tid + o];
                }
            }
            __syncthreads();
        }
        if (tid == 0) {
            g_topi[n * KTOP + k] = si[0];
            if (sp[0] >= 0) cv[sp[0]] = -CUDART_INF_F;
        }
        __syncthreads();
    }
}

// ---------------- final (prep fused) ----------------
__global__ __launch_bounds__(256) void final_kernel(const float* __restrict__ x,
                                                    const float* __restrict__ W,
                                                    const float* __restrict__ bvec,
                                                    float* __restrict__ out) {
    const int d = blockIdx.x;
    const int np = blockIdx.y;
    const int n = np & 3;
    const bool side1 = (np >= 4);
    const int tid = threadIdx.x;

    __shared__ float rS[128], rX[128], rY[128];
    __shared__ float s_e, s_wx, s_wy;
    if (tid < 128) {
        float pS = 0.0f, px = 0.0f, py = 0.0f;
        if (tid < KTOP) {
            int idx = g_topi[n * KTOP + tid];
            int r = side1 ? (idx % HW) : (idx / HW);
            float cx = (float)(r % WDIM) / 60.0f;
            float cy = (float)(r / WDIM) / 60.0f;
            float w0 = W[d * (2 * KTOP) + 2 * tid];
            float w1 = W[d * (2 * KTOP) + 2 * tid + 1];
            pS = fmaf(w0, cx, w1 * cy);
            px = w0; py = w1;
        }
        rS[tid] = pS; rX[tid] = px; rY[tid] = py;
    }
    __syncthreads();
    for (int o = 64; o > 0; o >>= 1) {
        if (tid < o) {
            rS[tid] += rS[tid + o];
            rX[tid] += rX[tid + o];
            rY[tid] += rY[tid + o];
        }
        __syncthreads();
    }
    if (tid == 0) {
        s_e = -rS[0] + bvec[d];
        s_wx = rX[0];
        s_wy = rY[0];
    }
    __syncthreads();
    const float wx = s_wx, wy = s_wy, e = s_e;
    const size_t base = ((size_t)np * CCH + d) * HW;
    for (int p = tid; p < HW; p += 256) {
        float gx = (float)(p % WDIM) / 60.0f;
        float gy = (float)(p / WDIM) / 60.0f;
        out[base + p] = x[base + p] + gx * wx + gy * wy + e;
    }
}

// ---------------- launch ----------------
extern "C" void kernel_launch(void* const* d_in, const int* in_sizes, int n_in,
                              void* d_out, int out_size) {
    (void)in_sizes; (void)n_in; (void)out_size;
    const float* x = (const float*)d_in[0];
    const float* W = (const float*)d_in[1];
    const float* b = (const float*)d_in[2];
    float* out = (float*)d_out;

    gemm_kernel<<<dim3(NBXS, NBY, NBATCH), 256>>>(x);
    colfin_kernel<<<dim3(LCPARTS, NBATCH), 256>>>();
    rowfin_kernel<<<dim3(LCPARTS, NBATCH), 256>>>();
    bound_kernel<<<NBATCH, 1024>>>();
    collect_kernel<<<dim3(64, NBATCH), 128>>>();
    select_kernel<<<NBATCH, 256>>>();
    final_kernel<<<dim3(CCH, 8), 256>>>(x, W, b, out);
}

// round 17
// speedup vs baseline: 1.9119x; 1.0622x over previous
#include <cuda_runtime.h>
#include <cuda_fp16.h>
#include <math_constants.h>
#include <stdint.h>

#define HW    3600
#define WDIM  60
#define CCH   128
#define NBATCH 4
#define KTOP  100
#define CAP   65536
#define NBX   29          // 128-wide blocks in both dims
#define LCPARTS 15
#define SPH   136

// ---------------- device scratch ----------------
__device__ float g_sm[(size_t)NBATCH * HW * HW];
__device__ float g_rp[NBATCH * NBX * HW];
__device__ float g_cp[NBATCH * NBX * HW];
__device__ float g_vp[NBATCH * NBX * HW];
__device__ float g_LR[NBATCH * HW];
__device__ float g_LC[NBATCH * HW];
__device__ float g_vmax[NBATCH * HW];
__device__ float g_rowbound[NBATCH * HW];
__device__ float g_lcmin_blk[NBATCH * NBX];
__device__ float g_lcmax_part[NBATCH * LCPARTS];
__device__ float g_thrv[NBATCH];
__device__ int   g_cnt[NBATCH];
__device__ int   g_rowcnt[NBATCH];
__device__ int   g_rowlist[NBATCH * HW];
__device__ float g_cv[NBATCH * CAP];
__device__ int   g_ci[NBATCH * CAP];
__device__ int   g_topi[NBATCH * KTOP];

// ---------------- helpers ----------------
__device__ __forceinline__ void mma_f16(float c[4], const unsigned a[4], const unsigned b[2]) {
    asm volatile(
        "mma.sync.aligned.m16n8k16.row.col.f32.f16.f16.f32 "
        "{%0,%1,%2,%3}, {%4,%5,%6,%7}, {%8,%9}, {%0,%1,%2,%3};"
        : "+f"(c[0]), "+f"(c[1]), "+f"(c[2]), "+f"(c[3])
        : "r"(a[0]), "r"(a[1]), "r"(a[2]), "r"(a[3]), "r"(b[0]), "r"(b[1]));
}
__device__ __forceinline__ unsigned mono_bits(float f) {
    unsigned b = __float_as_uint(f);
    return (b & 0x80000000u) ? ~b : (b | 0x80000000u);
}
__device__ __forceinline__ unsigned h2u(__half2 h) {
    return *reinterpret_cast<unsigned*>(&h);
}

// ---------------- GEMM: fp16 x3 split, 128x128 tile, 256 thr, 2 CTA/SM ----------------
// 8 warps in 4x2 grid, warp tile 32x64.
__global__ __launch_bounds__(256, 2) void gemm_kernel(const float* __restrict__ x) {
    __shared__ __align__(16) __half2 Ah[2][8][SPH];
    __shared__ __align__(16) __half2 Al[2][8][SPH];
    __shared__ __align__(16) __half2 Bh[2][8][SPH];
    __shared__ __align__(16) __half2 Bl[2][8][SPH];
    __shared__ float s_rs[2][128];
    __shared__ float s_rm[2][128];
    __shared__ float s_cs[4][128];

    const int n  = blockIdx.z;
    const int l0 = blockIdx.y * 128;
    const int s0 = blockIdx.x * 128;
    const float* A = x + (size_t)n * CCH * HW;
    const float* B = x + (size_t)(n + NBATCH) * CCH * HW;
    const int tid = threadIdx.x;
    const int lane = tid & 31;
    const int wid = tid >> 5;
    const int g = lane >> 2, tig = lane & 3;
    const int wm = wid & 3, wn = wid >> 2;
    const int rb = wm * 32, cb = wn * 64;

    const int kp = tid >> 5;            // 0..7
    const int m0 = lane << 2;           // 0..124
    const bool okA = (l0 + m0) < HW;
    const bool okB = (s0 + m0) < HW;

    float acc[2][8][4];
#pragma unroll
    for (int mi = 0; mi < 2; mi++)
#pragma unroll
        for (int ni = 0; ni < 8; ni++)
#pragma unroll
            for (int q = 0; q < 4; q++) acc[mi][ni][q] = 0.0f;

    float4 rA0, rA1, rB0, rB1;

    auto ldg_chunk = [&](int c) {
        const int d = c * 16 + kp * 2;
        rA0 = okA ? *reinterpret_cast<const float4*>(A + (size_t)d * HW + l0 + m0)
                  : make_float4(0.f, 0.f, 0.f, 0.f);
        rA1 = okA ? *reinterpret_cast<const float4*>(A + (size_t)(d + 1) * HW + l0 + m0)
                  : make_float4(0.f, 0.f, 0.f, 0.f);
        rB0 = okB ? *reinterpret_cast<const float4*>(B + (size_t)d * HW + s0 + m0)
                  : make_float4(0.f, 0.f, 0.f, 0.f);
        rB1 = okB ? *reinterpret_cast<const float4*>(B + (size_t)(d + 1) * HW + s0 + m0)
                  : make_float4(0.f, 0.f, 0.f, 0.f);
    };
    auto cvt_sts = [&](int st) {
        {
            __half2 h0 = __floats2half2_rn(rA0.x, rA1.x);
            __half2 h1 = __floats2half2_rn(rA0.y, rA1.y);
            __half2 h2 = __floats2half2_rn(rA0.z, rA1.z);
            __half2 h3 = __floats2half2_rn(rA0.w, rA1.w);
            float2 b0 = __half22float2(h0), b1 = __half22float2(h1);
            float2 b2 = __half22float2(h2), b3 = __half22float2(h3);
            __half2 L0 = __floats2half2_rn(rA0.x - b0.x, rA1.x - b0.y);
            __half2 L1 = __floats2half2_rn(rA0.y - b1.x, rA1.y - b1.y);
            __half2 L2 = __floats2half2_rn(rA0.z - b2.x, rA1.z - b2.y);
            __half2 L3 = __floats2half2_rn(rA0.w - b3.x, rA1.w - b3.y);
            *reinterpret_cast<uint4*>(&Ah[st][kp][m0]) = make_uint4(h2u(h0), h2u(h1), h2u(h2), h2u(h3));
            *reinterpret_cast<uint4*>(&Al[st][kp][m0]) = make_uint4(h2u(L0), h2u(L1), h2u(L2), h2u(L3));
        }
        {
            __half2 h0 = __floats2half2_rn(rB0.x, rB1.x);
            __half2 h1 = __floats2half2_rn(rB0.y, rB1.y);
            __half2 h2 = __floats2half2_rn(rB0.z, rB1.z);
            __half2 h3 = __floats2half2_rn(rB0.w, rB1.w);
            float2 b0 = __half22float2(h0), b1 = __half22float2(h1);
            float2 b2 = __half22float2(h2), b3 = __half22float2(h3);
            __half2 L0 = __floats2half2_rn(rB0.x - b0.x, rB1.x - b0.y);
            __half2 L1 = __floats2half2_rn(rB0.y - b1.x, rB1.y - b1.y);
            __half2 L2 = __floats2half2_rn(rB0.z - b2.x, rB1.z - b2.y);
            __half2 L3 = __floats2half2_rn(rB0.w - b3.x, rB1.w - b3.y);
            *reinterpret_cast<uint4*>(&Bh[st][kp][m0]) = make_uint4(h2u(h0), h2u(h1), h2u(h2), h2u(h3));
            *reinterpret_cast<uint4*>(&Bl[st][kp][m0]) = make_uint4(h2u(L0), h2u(L1), h2u(L2), h2u(L3));
        }
    };

    ldg_chunk(0);
    cvt_sts(0);
    ldg_chunk(1);
    __syncthreads();

#pragma unroll
    for (int c = 0; c < 8; c++) {
        const int st = c & 1;
        unsigned ah[2][4], al[2][4];
#pragma unroll
        for (int mi = 0; mi < 2; mi++) {
            const int mp = rb + mi * 16 + g;
            ah[mi][0] = h2u(Ah[st][tig][mp]);
            ah[mi][1] = h2u(Ah[st][tig][mp + 8]);
            ah[mi][2] = h2u(Ah[st][tig + 4][mp]);
            ah[mi][3] = h2u(Ah[st][tig + 4][mp + 8]);
            al[mi][0] = h2u(Al[st][tig][mp]);
            al[mi][1] = h2u(Al[st][tig][mp + 8]);
            al[mi][2] = h2u(Al[st][tig + 4][mp]);
            al[mi][3] = h2u(Al[st][tig + 4][mp + 8]);
        }
        if (c < 7) cvt_sts(st ^ 1);
        if (c < 6) ldg_chunk(c + 2);

        // b-fragments in two ni-halves to bound register pressure
#pragma unroll
        for (int h = 0; h < 2; h++) {
            unsigned bh[4][2], bl[4][2];
#pragma unroll
            for (int nj = 0; nj < 4; nj++) {
                const int np = cb + (h * 4 + nj) * 8 + g;
                bh[nj][0] = h2u(Bh[st][tig][np]);
                bh[nj][1] = h2u(Bh[st][tig + 4][np]);
                bl[nj][0] = h2u(Bl[st][tig][np]);
                bl[nj][1] = h2u(Bl[st][tig + 4][np]);
            }
#pragma unroll
            for (int mi = 0; mi < 2; mi++)
#pragma unroll
                for (int nj = 0; nj < 4; nj++)
                    mma_f16(acc[mi][h * 4 + nj], ah[mi], bl[nj]);
#pragma unroll
            for (int mi = 0; mi < 2; mi++)
#pragma unroll
                for (int nj = 0; nj < 4; nj++)
                    mma_f16(acc[mi][h * 4 + nj], al[mi], bh[nj]);
#pragma unroll
            for (int mi = 0; mi < 2; mi++)
#pragma unroll
                for (int nj = 0; nj < 4; nj++)
                    mma_f16(acc[mi][h * 4 + nj], ah[mi], bh[nj]);
        }
        __syncthreads();
    }

    // ---- epilogue ----
    const float inv = 1.0f / 12.8f;
    float rsum[2][2], rmax[2][2], csum[8][2];
#pragma unroll
    for (int i = 0; i < 2; i++)
#pragma unroll
        for (int r = 0; r < 2; r++) { rsum[i][r] = 0.0f; rmax[i][r] = -CUDART_INF_F; }
#pragma unroll
    for (int i = 0; i < 8; i++) { csum[i][0] = 0.0f; csum[i][1] = 0.0f; }

#pragma unroll
    for (int mi = 0; mi < 2; mi++) {
        const int row0 = l0 + rb + mi * 16 + g;
        const int row1 = row0 + 8;
        const bool rv0 = row0 < HW, rv1 = row1 < HW;
        float* orow0 = g_sm + ((size_t)(n * HW + row0)) * HW;
        float* orow1 = g_sm + ((size_t)(n * HW + row1)) * HW;
#pragma unroll
        for (int ni = 0; ni < 8; ni++) {
            const int sc0 = s0 + cb + ni * 8 + tig * 2;
            const bool cv0 = sc0 < HW, cv1 = (sc0 + 1) < HW;
            float v0 = acc[mi][ni][0] * inv;
            float v1 = acc[mi][ni][1] * inv;
            float v2 = acc[mi][ni][2] * inv;
            float v3 = acc[mi][ni][3] * inv;
            if (rv0 && cv0) *reinterpret_cast<float2*>(orow0 + sc0) = make_float2(v0, v1);
            if (rv1 && cv0) *reinterpret_cast<float2*>(orow1 + sc0) = make_float2(v2, v3);
            float e0 = cv0 ? __expf(v0) : 0.0f;
            float e1 = cv1 ? __expf(v1) : 0.0f;
            float e2 = cv0 ? __expf(v2) : 0.0f;
            float e3 = cv1 ? __expf(v3) : 0.0f;
            rsum[mi][0] += e0 + e1;
            rsum[mi][1] += e2 + e3;
            rmax[mi][0] = fmaxf(rmax[mi][0], fmaxf(cv0 ? v0 : -CUDART_INF_F, cv1 ? v1 : -CUDART_INF_F));
            rmax[mi][1] = fmaxf(rmax[mi][1], fmaxf(cv0 ? v2 : -CUDART_INF_F, cv1 ? v3 : -CUDART_INF_F));
            csum[ni][0] += (rv0 ? e0 : 0.0f) + (rv1 ? e2 : 0.0f);
            csum[ni][1] += (rv0 ? e1 : 0.0f) + (rv1 ? e3 : 0.0f);
        }
    }

#pragma unroll
    for (int m = 1; m < 4; m <<= 1) {
#pragma unroll
        for (int mi = 0; mi < 2; mi++)
#pragma unroll
            for (int r = 0; r < 2; r++) {
                rsum[mi][r] += __shfl_xor_sync(0xffffffffu, rsum[mi][r], m);
                rmax[mi][r] = fmaxf(rmax[mi][r], __shfl_xor_sync(0xffffffffu, rmax[mi][r], m));
            }
    }
    if (tig == 0) {
#pragma unroll
        for (int mi = 0; mi < 2; mi++) {
            const int rr = rb + mi * 16 + g;
            s_rs[wn][rr] = rsum[mi][0];
            s_rs[wn][rr + 8] = rsum[mi][1];
            s_rm[wn][rr] = rmax[mi][0];
            s_rm[wn][rr + 8] = rmax[mi][1];
        }
    }
#pragma unroll
    for (int m = 4; m < 32; m <<= 1) {
#pragma unroll
        for (int ni = 0; ni < 8; ni++)
#pragma unroll
            for (int q = 0; q < 2; q++)
                csum[ni][q] += __shfl_xor_sync(0xffffffffu, csum[ni][q], m);
    }
    if (g == 0) {
#pragma unroll
        for (int ni = 0; ni < 8; ni++) {
            s_cs[wm][cb + ni * 8 + tig * 2]     = csum[ni][0];
            s_cs[wm][cb + ni * 8 + tig * 2 + 1] = csum[ni][1];
        }
    }
    __syncthreads();
    if (tid < 128) {
        if (l0 + tid < HW) {
            float rs = s_rs[0][tid] + s_rs[1][tid];
            float rm = fmaxf(s_rm[0][tid], s_rm[1][tid]);
            g_rp[(n * NBX + blockIdx.x) * HW + l0 + tid] = rs;
            g_vp[(n * NBX + blockIdx.x) * HW + l0 + tid] = rm;
        }
        if (s0 + tid < HW) {
            float cs = s_cs[0][tid] + s_cs[1][tid] + s_cs[2][tid] + s_cs[3][tid];
            g_cp[(n * NBX + blockIdx.y) * HW + s0 + tid] = cs;
        }
    }
}

// ---------------- colfin ----------------
__global__ __launch_bounds__(256) void colfin_kernel() {
    const int n = blockIdx.y;
    const int s = blockIdx.x * 256 + threadIdx.x;
    __shared__ float mn[256], mx[256];
    float v = CUDART_INF_F;
    float hi = -CUDART_INF_F;
    if (s < HW) {
        float acc = 0.0f;
#pragma unroll
        for (int b = 0; b < NBX; b++) acc += g_cp[(n * NBX + b) * HW + s];
        v = logf(acc);
        g_LC[n * HW + s] = v;
        hi = v;
    }
    const int tid = threadIdx.x;
    mn[tid] = v; mx[tid] = hi;
    __syncthreads();
    for (int o = 64; o > 0; o >>= 1) {
        if ((tid & 127) < o) mn[tid] = fminf(mn[tid], mn[tid + o]);
        __syncthreads();
    }
    if ((tid & 127) == 0) {
        int blk = (blockIdx.x * 256 + tid) >> 7;
        if (blk < NBX) g_lcmin_blk[n * NBX + blk] = mn[tid];
    }
    for (int o = 128; o > 0; o >>= 1) {
        if (tid < o) mx[tid] = fmaxf(mx[tid], mx[tid + o]);
        __syncthreads();
    }
    if (tid == 0) g_lcmax_part[n * LCPARTS + blockIdx.x] = mx[0];
}

// ---------------- rowfin ----------------
__global__ __launch_bounds__(256) void rowfin_kernel() {
    const int n = blockIdx.y;
    const int l = blockIdx.x * 256 + threadIdx.x;
    __shared__ float lcb[NBX];
    if (threadIdx.x < NBX) lcb[threadIdx.x] = g_lcmin_blk[n * NBX + threadIdx.x];
    __syncthreads();
    if (l >= HW) return;
    float s = 0.0f, m = -CUDART_INF_F, rbnd = -CUDART_INF_F;
#pragma unroll
    for (int b = 0; b < NBX; b++) {
        float vp = g_vp[(n * NBX + b) * HW + l];
        s += g_rp[(n * NBX + b) * HW + l];
        m = fmaxf(m, vp);
        rbnd = fmaxf(rbnd, fmaf(2.0f, vp, -lcb[b]));
    }
    float LR = logf(s);
    g_LR[n * HW + l] = LR;
    g_vmax[n * HW + l] = m;
    g_rowbound[n * HW + l] = rbnd - LR;
}

// ---------------- threshold + row compaction ----------------
__global__ __launch_bounds__(1024) void bound_kernel() {
    const int n = blockIdx.x;
    const int tid = threadIdx.x;
    __shared__ float Lbuf[HW];
    __shared__ float red1[1024], red2[1024];
    __shared__ int hist[2048];
    __shared__ unsigned ssum[1024];
    __shared__ float s_lmn, s_lmx, s_lcmax, s_t;

    {
        float v = (tid < LCPARTS) ? g_lcmax_part[n * LCPARTS + tid] : -CUDART_INF_F;
        red1[tid] = v;
        __syncthreads();
        for (int o = 16; o > 0; o >>= 1) {
            if (tid < o) red1[tid] = fmaxf(red1[tid], red1[tid + o]);
            __syncthreads();
        }
        if (tid == 0) {
            s_lcmax = red1[0];
            g_cnt[n] = 0;
            g_rowcnt[n] = 0;
        }
    }
    __syncthreads();
    const float lcmax = s_lcmax;

    float lmn = CUDART_INF_F, lmx = -CUDART_INF_F;
    for (int l = tid; l < HW; l += 1024) {
        float L = fmaf(2.0f, g_vmax[n * HW + l], -g_LR[n * HW + l]) - lcmax;
        Lbuf[l] = L;
        lmn = fminf(lmn, L); lmx = fmaxf(lmx, L);
    }
    red1[tid] = lmn; red2[tid] = lmx;
    __syncthreads();
    for (int o = 512; o > 0; o >>= 1) {
        if (tid < o) {
            red1[tid] = fminf(red1[tid], red1[tid + o]);
            red2[tid] = fmaxf(red2[tid], red2[tid + o]);
        }
        __syncthreads();
    }
    if (tid == 0) { s_lmn = red1[0]; s_lmx = red2[0]; }
    __syncthreads();
    const float Lmn = s_lmn;
    const float binw = (s_lmx - Lmn) * (1.0f / 2048.0f);

    if (binw < 1e-30f) {
        if (tid == 0) s_t = Lmn;
    } else {
        for (int i = tid; i < 2048; i += 1024) hist[i] = 0;
        __syncthreads();
        for (int l = tid; l < HW; l += 1024) {
            int b = (int)((Lbuf[l] - Lmn) / binw);
            b = max(0, min(2047, b));
            atomicAdd(&hist[b], 1);
        }
        __syncthreads();
        unsigned csum = (unsigned)hist[tid * 2] + (unsigned)hist[tid * 2 + 1];
        ssum[tid] = csum;
        __syncthreads();
        for (int off = 1; off < 1024; off <<= 1) {
            unsigned v = (tid + off < 1024) ? ssum[tid + off] : 0u;
            __syncthreads();
            ssum[tid] += v;
            __syncthreads();
        }
        unsigned mine = ssum[tid];
        unsigned nxt = (tid < 1023) ? ssum[tid + 1] : 0u;
        if (mine >= KTOP && nxt < KTOP) {
            unsigned cum = nxt;
            int b = tid * 2 + 1;
            for (; b > tid * 2; b--) {
                cum += (unsigned)hist[b];
                if (cum >= KTOP) break;
            }
            s_t = Lmn + (float)(b - 1) * binw;
        }
    }
    __syncthreads();
    const float t = s_t;
    if (tid == 0) g_thrv[n] = t;
    for (int l = tid; l < HW; l += 1024) {
        if (g_rowbound[n * HW + l] >= t) {
            int p = atomicAdd(&g_rowcnt[n], 1);
            g_rowlist[n * HW + p] = l;
        }
    }
}

// ---------------- collect ----------------
__global__ __launch_bounds__(128) void collect_kernel() {
    const int n = blockIdx.y;
    const float t = g_thrv[n];
    const int rcnt = g_rowcnt[n];
    const int tid = threadIdx.x;
    __shared__ unsigned s_mask;
    const float* LC = g_LC + n * HW;

    for (int ri = blockIdx.x; ri < rcnt; ri += gridDim.x) {
        const int l = g_rowlist[n * HW + ri];
        const float LR = g_LR[n * HW + l];
        if (tid < 32) {
            bool flag = false;
            if (tid < NBX) {
                float vp = g_vp[(n * NBX + tid) * HW + l];
                flag = (fmaf(2.0f, vp, -LR) - g_lcmin_blk[n * NBX + tid]) >= t;
            }
            unsigned m = __ballot_sync(0xffffffffu, flag);
            if (tid == 0) s_mask = m;
        }
        __syncthreads();
        unsigned mask = s_mask;
        const float* row = g_sm + ((size_t)(n * HW + l)) * HW;
        while (mask) {
            int b = __ffs(mask) - 1;
            mask &= mask - 1;
            int s = b * 128 + tid;
            if (s < HW) {
                float sc = fmaf(2.0f, row[s], -LR) - LC[s];
                if (sc >= t) {
                    int p = atomicAdd(&g_cnt[n], 1);
                    if (p < CAP) {
                        g_cv[n * CAP + p] = sc;
                        g_ci[n * CAP + p] = l * HW + s;
                    }
                }
            }
        }
        __syncthreads();
    }
}

// ---------------- select ----------------
__global__ __launch_bounds__(256) void select_kernel() {
    const int n = blockIdx.x;
    const int tid = threadIdx.x;
    int cnt = g_cnt[n];
    if (cnt > CAP) cnt = CAP;
    float* cv = g_cv + n * CAP;
    int* ci = g_ci + n * CAP;

    if (cnt <= 2048) {
        __shared__ unsigned long long key[2048];
        for (int i = tid; i < 2048; i += 256) {
            unsigned long long k = 0ull;
            if (i < cnt)
                k = ((unsigned long long)mono_bits(cv[i]) << 32) |
                    (unsigned long long)(0xFFFFFFFFu - (unsigned)ci[i]);
            key[i] = k;
        }
        __syncthreads();
        for (int kk = 2; kk <= 2048; kk <<= 1) {
            for (int j = kk >> 1; j > 0; j >>= 1) {
                for (int i = tid; i < 2048; i += 256) {
                    int ixj = i ^ j;
                    if (ixj > i) {
                        bool dirDesc = ((i & kk) == 0);
                        unsigned long long a = key[i], b = key[ixj];
                        if ((a < b) == dirDesc) { key[i] = b; key[ixj] = a; }
                    }
                }
                __syncthreads();
            }
        }
        if (tid < KTOP)
            g_topi[n * KTOP + tid] = (int)(0xFFFFFFFFu - (unsigned)(key[tid] & 0xFFFFFFFFull));
        return;
    }

    __shared__ float sv[256];
    __shared__ int si[256];
    __shared__ int sp[256];
    for (int k = 0; k < KTOP; k++) {
        float bv = -CUDART_INF_F; int bi = 0x7FFFFFFF; int bp = -1;
        for (int j = tid; j < cnt; j += 256) {
            float v = cv[j]; int idx = ci[j];
            if (v > bv || (v == bv && idx < bi)) { bv = v; bi = idx; bp = j; }
        }
        sv[tid] = bv; si[tid] = bi; sp[tid] = bp;
        __syncthreads();
        for (int o = 128; o > 0; o >>= 1) {
            if (tid < o) {
                if (sv[tid + o] > sv[tid] || (sv[tid + o] == sv[tid] && si[tid + o] < si[tid])) {
                    sv[tid] = sv[tid + o]; si[tid] = si[tid + o]; sp[tid] = sp[tid + o];
                }
            }
            __syncthreads();
        }
        if (tid == 0) {
            g_topi[n * KTOP + k] = si[0];
            if (sp[0] >= 0) cv[sp[0]] = -CUDART_INF_F;
        }
        __syncthreads();
    }
}

// ---------------- final (prep fused) ----------------
__global__ __launch_bounds__(256) void final_kernel(const float* __restrict__ x,
                                                    const float* __restrict__ W,
                                                    const float* __restrict__ bvec,
                                                    float* __restrict__ out) {
    const int d = blockIdx.x;
    const int np = blockIdx.y;
    const int n = np & 3;
    const bool side1 = (np >= 4);
    const int tid = threadIdx.x;

    __shared__ float rS[128], rX[128], rY[128];
    __shared__ float s_e, s_wx, s_wy;
    if (tid < 128) {
        float pS = 0.0f, px = 0.0f, py = 0.0f;
        if (tid < KTOP) {
            int idx = g_topi[n * KTOP + tid];
            int r = side1 ? (idx % HW) : (idx / HW);
            float cx = (float)(r % WDIM) / 60.0f;
            float cy = (float)(r / WDIM) / 60.0f;
            float w0 = W[d * (2 * KTOP) + 2 * tid];
            float w1 = W[d * (2 * KTOP) + 2 * tid + 1];
            pS = fmaf(w0, cx, w1 * cy);
            px = w0; py = w1;
        }
        rS[tid] = pS; rX[tid] = px; rY[tid] = py;
    }
    __syncthreads();
    for (int o = 64; o > 0; o >>= 1) {
        if (tid < o) {
            rS[tid] += rS[tid + o];
            rX[tid] += rX[tid + o];
            rY[tid] += rY[tid + o];
        }
        __syncthreads();
    }
    if (tid == 0) {
        s_e = -rS[0] + bvec[d];
        s_wx = rX[0];
        s_wy = rY[0];
    }
    __syncthreads();
    const float wx = s_wx, wy = s_wy, e = s_e;
    const size_t base = ((size_t)np * CCH + d) * HW;
    for (int p = tid; p < HW; p += 256) {
        float gx = (float)(p % WDIM) / 60.0f;
        float gy = (float)(p / WDIM) / 60.0f;
        out[base + p] = x[base + p] + gx * wx + gy * wy + e;
    }
}

// ---------------- launch ----------------
extern "C" void kernel_launch(void* const* d_in, const int* in_sizes, int n_in,
                              void* d_out, int out_size) {
    (void)in_sizes; (void)n_in; (void)out_size;
    const float* x = (const float*)d_in[0];
    const float* W = (const float*)d_in[1];
    const float* b = (const float*)d_in[2];
    float* out = (float*)d_out;

    gemm_kernel<<<dim3(NBX, NBX, NBATCH), 256>>>(x);
    colfin_kernel<<<dim3(LCPARTS, NBATCH), 256>>>();
    rowfin_kernel<<<dim3(LCPARTS, NBATCH), 256>>>();
    bound_kernel<<<NBATCH, 1024>>>();
    collect_kernel<<<dim3(148, NBATCH), 128>>>();
    select_kernel<<<NBATCH, 256>>>();
    final_kernel<<<dim3(CCH, 8), 256>>>(x, W, b, out);
}